// round 6
// baseline (speedup 1.0000x reference)
#include <cuda_runtime.h>
#include <cuda_fp16.h>
#include <cstdint>

// ---------------------------------------------------------------------------
// GCN_8796093022507: 2-layer GCN, dropout 0.6, N=100000, E=6.4M.
// R6: edge passes stage the 200KB fp16 payload table into dynamic SMEM
// (1 fat block/SM, 1024 thr) -> random gathers become LDS (conflict ~4)
// instead of ~1 L1tex wavefront/edge. Atomics remain global REDG (the floor).
// PRNG: JAX threefry2x32, partitionable (verified).
// ---------------------------------------------------------------------------

#define NMAX 100000
#define TAB_BYTES (NMAX * 2)          // 200000 B fp16 table
#define TAB_INT4  (TAB_BYTES / 16)    // 12500 exact

__device__ int      g_deg[NMAX];
__device__ float    g_dinv[NMAX];
__device__ __align__(16) __half g_u[NMAX];   // layer1 payload: dropout1(x)*dinv
__device__ __align__(16) __half g_w[NMAX];   // layer2 payload: t*dinv
__device__ float    g_acc1[NMAX];
__device__ float    g_acc2[NMAX];
__device__ unsigned g_key[4];
__device__ int      g_is64;

__device__ __forceinline__ uint2 tf2x32(unsigned k0, unsigned k1,
                                        unsigned x0, unsigned x1) {
  unsigned k2 = k0 ^ k1 ^ 0x1BD11BDAu;
  x0 += k0; x1 += k1;
#define TFR(r) { x0 += x1; x1 = (x1 << (r)) | (x1 >> (32 - (r))); x1 ^= x0; }
  TFR(13) TFR(15) TFR(26) TFR(6)
  x0 += k1; x1 += k2 + 1u;
  TFR(17) TFR(29) TFR(16) TFR(24)
  x0 += k2; x1 += k0 + 2u;
  TFR(13) TFR(15) TFR(26) TFR(6)
  x0 += k0; x1 += k1 + 3u;
  TFR(17) TFR(29) TFR(16) TFR(24)
  x0 += k1; x1 += k2 + 4u;
  TFR(13) TFR(15) TFR(26) TFR(6)
  x0 += k2; x1 += k0 + 5u;
#undef TFR
  return make_uint2(x0, x1);
}

__device__ __forceinline__ bool keep40(unsigned k0, unsigned k1, unsigned i) {
  uint2 z = tf2x32(k0, k1, 0u, i);
  unsigned bits = z.x ^ z.y;
  float u = __uint_as_float((bits >> 9) | 0x3F800000u) - 1.0f;
  return u < 0.4f;
}

__global__ void k_init(const void* ei, int E, int N) {
  int i = blockIdx.x * blockDim.x + threadIdx.x;
  if (i < N) { g_deg[i] = 0; g_acc1[i] = 0.0f; g_acc2[i] = 0.0f; }
  if (i == 0) {
    const long long* p = (const long long*)ei;
    bool ok64 = true;
    for (int k = 0; k < 4; k++) {
      long long v = p[k];
      if (v < 0 || v >= (long long)N) ok64 = false;
    }
    g_is64 = ok64 ? 1 : 0;
    uint2 ka = tf2x32(0u, 42u, 0u, 0u);
    uint2 kb = tf2x32(0u, 42u, 0u, 1u);
    g_key[0] = ka.x; g_key[1] = ka.y;
    g_key[2] = kb.x; g_key[3] = kb.y;
  }
}

// In-degree histogram over the dst row, 4 edges per thread.
__global__ void k_deg(const void* ei, int nquads, int E, int N) {
  int i = blockIdx.x * blockDim.x + threadIdx.x;
  if (i >= nquads) return;
  int e0 = 4 * i;
  if (g_is64) {
    const long long* dstr = (const long long*)ei + E;
    #pragma unroll
    for (int k = 0; k < 4; k++) {
      if (e0 + k < E) {
        int d = (int)dstr[e0 + k];
        if ((unsigned)d < (unsigned)N) atomicAdd(&g_deg[d], 1);
      }
    }
  } else {
    const int* dstr = (const int*)ei + E;
    if (e0 + 3 < E) {
      int4 d4 = ((const int4*)dstr)[i];
      atomicAdd(&g_deg[d4.x], 1);
      atomicAdd(&g_deg[d4.y], 1);
      atomicAdd(&g_deg[d4.z], 1);
      atomicAdd(&g_deg[d4.w], 1);
    } else {
      for (int k = 0; k < 4 && e0 + k < E; k++)
        atomicAdd(&g_deg[dstr[e0 + k]], 1);
    }
  }
}

__global__ void k_node1(const float* __restrict__ x, int N) {
  int i = blockIdx.x * blockDim.x + threadIdx.x;
  if (i >= N) return;
  int d = g_deg[i];
  float dinv = (d > 0) ? rsqrtf((float)d) : 0.0f;
  g_dinv[i] = dinv;
  float u = keep40(g_key[0], g_key[1], (unsigned)i) ? x[i] * 2.5f * dinv : 0.0f;
  g_u[i] = __float2half(u);
}

// Edge scatter with SMEM-staged payload table. LAYER=0: u->acc1, 1: w->acc2.
template <int LAYER>
__global__ void k_edge_smem(const void* ei, int E, int chunk) {
  extern __shared__ __half s_tab[];
  int tid = threadIdx.x;
  // Stage the fp16 payload table (200KB) into SMEM, int4-vectorized.
  {
    const int4* src = (const int4*)(LAYER == 0 ? g_u : g_w);
    int4* dst = (int4*)s_tab;
    for (int i = tid; i < TAB_INT4; i += blockDim.x) dst[i] = src[i];
  }
  __syncthreads();

  long long base = (long long)blockIdx.x * chunk;
  long long end  = base + chunk; if (end > E) end = E;
  float* acc = (LAYER == 0) ? g_acc1 : g_acc2;

  if (g_is64) {
    const long long* sp = (const long long*)ei;
    const long long* dp = sp + E;
    for (long long e = base + tid; e < end; e += blockDim.x) {
      int s = (int)sp[e], d = (int)dp[e];
      float v = __half2float(s_tab[s]);
      if (v != 0.0f) atomicAdd(&acc[d], v);
    }
  } else {
    const int* sp = (const int*)ei;
    const int* dp = sp + E;
    for (long long e = base + tid; e < end; e += blockDim.x) {
      int s = sp[e], d = dp[e];
      float v = __half2float(s_tab[s]);
      if (v != 0.0f) atomicAdd(&acc[d], v);
    }
  }
}

__global__ void k_node2(const float* __restrict__ W1, const float* __restrict__ b1,
                        const float* __restrict__ W2, int N) {
  int tid = blockIdx.x * blockDim.x + threadIdx.x;
  int n = tid >> 4, j = tid & 15;
  if (n >= N) return;
  float dinv = g_dinv[n];
  float s1 = g_acc1[n] * dinv;                                 // finish layer1
  float v = fmaxf(s1 * __ldg(&W1[j]) + __ldg(&b1[j]), 0.0f);   // relu
  unsigned i = (unsigned)n * 16u + (unsigned)j;
  v = keep40(g_key[2], g_key[3], i) ? v * 2.5f : 0.0f;         // dropout2
  v *= __ldg(&W2[j]);
  #pragma unroll
  for (int off = 8; off; off >>= 1)
    v += __shfl_xor_sync(0xFFFFFFFFu, v, off, 16);
  if (j == 0) g_w[n] = __float2half(v * dinv);                 // payload = t*dinv
}

__global__ void k_node3(const float* __restrict__ b2, float* __restrict__ out, int N) {
  int i = blockIdx.x * blockDim.x + threadIdx.x;
  if (i >= N) return;
  out[i] = g_acc2[i] * g_dinv[i] + b2[0];
}

extern "C" void kernel_launch(void* const* d_in, const int* in_sizes, int n_in,
                              void* d_out, int out_size) {
  const float* x  = (const float*)d_in[0];
  const void*  ei = d_in[1];
  const float* W1 = (const float*)d_in[2];
  const float* b1 = (const float*)d_in[3];
  const float* W2 = (const float*)d_in[4];
  const float* b2 = (const float*)d_in[5];
  float* out = (float*)d_out;

  int N = in_sizes[0];
  int E = in_sizes[1] / 2;

  static int smCount = 0;
  if (smCount == 0) {
    cudaDeviceGetAttribute(&smCount, cudaDevAttrMultiProcessorCount, 0);
    if (smCount <= 0) smCount = 148;
    cudaFuncSetAttribute(k_edge_smem<0>,
                         cudaFuncAttributeMaxDynamicSharedMemorySize, TAB_BYTES);
    cudaFuncSetAttribute(k_edge_smem<1>,
                         cudaFuncAttributeMaxDynamicSharedMemorySize, TAB_BYTES);
  }

  const int TB = 256;
  int nblkN   = (N + TB - 1) / TB;
  int nquads  = (E + 3) / 4;
  int nblkQ   = (nquads + TB - 1) / TB;
  int nblkN16 = (N * 16 + TB - 1) / TB;
  int chunk   = (E + smCount - 1) / smCount;

  k_init <<<nblkN,  TB>>>(ei, E, N);
  k_deg  <<<nblkQ,  TB>>>(ei, nquads, E, N);
  k_node1<<<nblkN,  TB>>>(x, N);
  k_edge_smem<0><<<smCount, 1024, TAB_BYTES>>>(ei, E, chunk);
  k_node2<<<nblkN16, TB>>>(W1, b1, W2, N);
  k_edge_smem<1><<<smCount, 1024, TAB_BYTES>>>(ei, E, chunk);
  k_node3<<<nblkN,  TB>>>(b2, out, N);
}